// round 7
// baseline (speedup 1.0000x reference)
#include <cuda_runtime.h>
#include <cuda_bf16.h>
#include <math.h>
#include <stdint.h>

#define DIM     1024
#define HEADS   16
#define DHEAD   64
#define INNER   1024
#define BATCH   4
#define NTOK    4096
#define MTOT    (BATCH * NTOK)      // 16384
#define QKVN    (3 * INNER)         // 3072
#define NSPLIT  32

// ---------------------------------------------------------------------------
// Scratch (device globals; no runtime allocation allowed)
// ---------------------------------------------------------------------------
__device__ float g_qkv[(size_t)MTOT * QKVN];                                 // 192 MB
__device__ float g_part[(size_t)NSPLIT * BATCH * HEADS * DHEAD * DHEAD];     // 32 MB
__device__ float g_C[(size_t)BATCH * HEADS * DHEAD * DHEAD];                 // 1 MB

// Packed bf16 hi/lo (row-major A [M][K]; transposed B [N][K])
__device__ __nv_bfloat16 g_xh[(size_t)MTOT * DIM];
__device__ __nv_bfloat16 g_xl[(size_t)MTOT * DIM];
__device__ __nv_bfloat16 g_uh[(size_t)MTOT * DIM];
__device__ __nv_bfloat16 g_ul[(size_t)MTOT * DIM];
__device__ __nv_bfloat16 g_wqh[(size_t)QKVN * DIM];   // [N=3072][K=1024]
__device__ __nv_bfloat16 g_wql[(size_t)QKVN * DIM];
__device__ __nv_bfloat16 g_woh[(size_t)INNER * DIM];  // [N=1024][K=1024]
__device__ __nv_bfloat16 g_wol[(size_t)INNER * DIM];

// ---------------------------------------------------------------------------
// helpers
// ---------------------------------------------------------------------------
__device__ __forceinline__ uint32_t smem_u32(const void* p) {
    uint32_t a;
    asm("{ .reg .u64 t; cvta.to.shared.u64 t, %1; cvt.u32.u64 %0, t; }"
        : "=r"(a) : "l"(p));
    return a;
}

__device__ __forceinline__ void cp_async16(uint32_t dst, const void* src) {
    asm volatile("cp.async.cg.shared.global [%0], [%1], 16;"
                 :: "r"(dst), "l"(src) : "memory");
}
__device__ __forceinline__ void cp_commit() {
    asm volatile("cp.async.commit_group;" ::: "memory");
}
template <int N>
__device__ __forceinline__ void cp_wait() {
    asm volatile("cp.async.wait_group %0;" :: "n"(N) : "memory");
}

__device__ __forceinline__ void ldm_x4(uint32_t& r0, uint32_t& r1,
                                       uint32_t& r2, uint32_t& r3, uint32_t a) {
    asm volatile("ldmatrix.sync.aligned.m8n8.x4.shared.b16 {%0,%1,%2,%3}, [%4];"
                 : "=r"(r0), "=r"(r1), "=r"(r2), "=r"(r3) : "r"(a));
}

__device__ __forceinline__ void mma_bf16(float& c0, float& c1, float& c2, float& c3,
                                         uint32_t a0, uint32_t a1, uint32_t a2, uint32_t a3,
                                         uint32_t b0, uint32_t b1) {
    asm volatile(
        "mma.sync.aligned.m16n8k16.row.col.f32.bf16.bf16.f32 "
        "{%0,%1,%2,%3}, {%4,%5,%6,%7}, {%8,%9}, {%0,%1,%2,%3};"
        : "+f"(c0), "+f"(c1), "+f"(c2), "+f"(c3)
        : "r"(a0), "r"(a1), "r"(a2), "r"(a3), "r"(b0), "r"(b1));
}

__device__ __forceinline__ void split_bf16(float f, ushort& h, ushort& l) {
    __nv_bfloat16 hi = __float2bfloat16(f);
    __nv_bfloat16 lo = __float2bfloat16(f - __bfloat162float(hi));
    h = __bfloat16_as_ushort(hi);
    l = __bfloat16_as_ushort(lo);
}

// ---------------------------------------------------------------------------
// bf16x3 GEMM via mma.sync: C[M,N] = A @ B^T (+bias)
// CTA tile 128x128, BK=32, 8 warps (4m x 2n). 2 CTAs/SM.
// Inner loop restructured: B fragments loaded per 16-col group and consumed
// immediately (peak live regs ~100, under the 128 cap).
// ---------------------------------------------------------------------------
#define BKC      32
#define ROWB     80                      // padded row bytes (40 bf16)
#define OPSZ     (128 * ROWB)            // 10240 B per operand tile
#define BUFSZ    (4 * OPSZ)              // 40960 B per buffer
#define GEMM_SMEM (2 * BUFSZ)            // 81920 B

__global__ __launch_bounds__(256, 2) void gemm_bf16x3_kernel(
    const __nv_bfloat16* __restrict__ Ah, const __nv_bfloat16* __restrict__ Al,
    const __nv_bfloat16* __restrict__ Bth, const __nv_bfloat16* __restrict__ Btl,
    float* __restrict__ C, const float* __restrict__ bias, int N, int K)
{
    extern __shared__ char smem[];
    const uint32_t sb = smem_u32(smem);
    const int tid = threadIdx.x;
    const int lane = tid & 31;
    const int wid = tid >> 5;
    const int wm = wid & 3;          // 0..3  (m)
    const int wn = wid >> 2;         // 0..1  (n)
    const int ntile = blockIdx.x;
    const int mtile = blockIdx.y;

    // ---- gmem -> smem assignment (cp.async, 16B each, 8 per thread/chunk)
    const int g = tid >> 6;          // operand 0..3 (Ah, Al, Bth, Btl)
    const int lt = tid & 63;
    const __nv_bfloat16* opsrc;
    if (g == 0)      opsrc = Ah  + (size_t)mtile * 128 * K;
    else if (g == 1) opsrc = Al  + (size_t)mtile * 128 * K;
    else if (g == 2) opsrc = Bth + (size_t)ntile * 128 * K;
    else             opsrc = Btl + (size_t)ntile * 128 * K;

    const int nchunks = K / BKC;

    auto issue_chunk = [&](int c, int buf) {
        const uint32_t dbase = sb + buf * BUFSZ + g * OPSZ;
#pragma unroll
        for (int i = 0; i < 8; i++) {
            int idx = lt + 64 * i;       // 0..511
            int row = idx >> 2;
            int seg = idx & 3;
            cp_async16(dbase + row * ROWB + seg * 16,
                       opsrc + (size_t)row * K + c * BKC + seg * 8);
        }
        cp_commit();
    };

    float acc[2][8][4];
#pragma unroll
    for (int im = 0; im < 2; im++)
#pragma unroll
        for (int jn = 0; jn < 8; jn++)
#pragma unroll
            for (int r = 0; r < 4; r++) acc[im][jn][r] = 0.f;

    const int at_tile = lane >> 3;
    const int a_row = (at_tile & 1) * 8 + (lane & 7);
    const int a_cadd = (at_tile >> 1) * 16;
    const int b_row = ((at_tile >> 1) * 8) + (lane & 7);
    const int b_cadd = (at_tile & 1) * 16;

    issue_chunk(0, 0);

    for (int c = 0; c < nchunks; c++) {
        const int buf = c & 1;
        if (c + 1 < nchunks) { issue_chunk(c + 1, buf ^ 1); cp_wait<1>(); }
        else                 { cp_wait<0>(); }
        __syncthreads();

        const uint32_t base = sb + buf * BUFSZ;
#pragma unroll
        for (int kk = 0; kk < 2; kk++) {
            const int kb = kk * 32;  // 16 elems = 32 bytes
            uint32_t ah[2][4], al[2][4];
#pragma unroll
            for (int im = 0; im < 2; im++) {
                uint32_t aoff = (uint32_t)(wm * 32 + im * 16 + a_row) * ROWB + kb + a_cadd;
                ldm_x4(ah[im][0], ah[im][1], ah[im][2], ah[im][3], base + 0 * OPSZ + aoff);
                ldm_x4(al[im][0], al[im][1], al[im][2], al[im][3], base + 1 * OPSZ + aoff);
            }
#pragma unroll
            for (int p = 0; p < 4; p++) {
                uint32_t bh4[4], bl4[4];
                uint32_t boff = (uint32_t)(wn * 64 + p * 16 + b_row) * ROWB + kb + b_cadd;
                ldm_x4(bh4[0], bh4[1], bh4[2], bh4[3], base + 2 * OPSZ + boff);
                ldm_x4(bl4[0], bl4[1], bl4[2], bl4[3], base + 3 * OPSZ + boff);
#pragma unroll
                for (int im = 0; im < 2; im++) {
#pragma unroll
                    for (int q2 = 0; q2 < 2; q2++) {
                        const int jn = p * 2 + q2;
                        const int q = q2 * 2;
                        float* cc = acc[im][jn];
                        mma_bf16(cc[0], cc[1], cc[2], cc[3],
                                 ah[im][0], ah[im][1], ah[im][2], ah[im][3],
                                 bh4[q], bh4[q + 1]);
                        mma_bf16(cc[0], cc[1], cc[2], cc[3],
                                 ah[im][0], ah[im][1], ah[im][2], ah[im][3],
                                 bl4[q], bl4[q + 1]);
                        mma_bf16(cc[0], cc[1], cc[2], cc[3],
                                 al[im][0], al[im][1], al[im][2], al[im][3],
                                 bh4[q], bh4[q + 1]);
                    }
                }
            }
        }
        __syncthreads();
    }

    // ---- epilogue
    const int m0 = mtile * 128 + wm * 32;
    const int n0 = ntile * 128 + wn * 64;
#pragma unroll
    for (int im = 0; im < 2; im++) {
#pragma unroll
        for (int jn = 0; jn < 8; jn++) {
            const int row = m0 + im * 16 + (lane >> 2);
            const int col = n0 + jn * 8 + (lane & 3) * 2;
            float b0 = bias ? bias[col] : 0.f;
            float b1 = bias ? bias[col + 1] : 0.f;
            float2 v0 = {acc[im][jn][0] + b0, acc[im][jn][1] + b1};
            float2 v1 = {acc[im][jn][2] + b0, acc[im][jn][3] + b1};
            *reinterpret_cast<float2*>(C + (size_t)row * N + col) = v0;
            *reinterpret_cast<float2*>(C + (size_t)(row + 8) * N + col) = v1;
        }
    }
}

// ---------------------------------------------------------------------------
// packA: fp32 [M][K] -> hi/lo bf16 [M][K] (row-major). 8 elems/thread.
// ---------------------------------------------------------------------------
__global__ __launch_bounds__(256) void packA_kernel(
    const float* __restrict__ A, __nv_bfloat16* __restrict__ H,
    __nv_bfloat16* __restrict__ L)
{
    const size_t e0 = ((size_t)blockIdx.x * 256 + threadIdx.x) * 8;
    float4 v0 = *reinterpret_cast<const float4*>(A + e0);
    float4 v1 = *reinterpret_cast<const float4*>(A + e0 + 4);
    float f[8] = {v0.x, v0.y, v0.z, v0.w, v1.x, v1.y, v1.z, v1.w};
    ushort h[8], l[8];
#pragma unroll
    for (int i = 0; i < 8; i++) split_bf16(f[i], h[i], l[i]);
    *reinterpret_cast<uint4*>(H + e0) = *reinterpret_cast<uint4*>(h);
    *reinterpret_cast<uint4*>(L + e0) = *reinterpret_cast<uint4*>(l);
}

// ---------------------------------------------------------------------------
// packBt: fp32 W[K][N] -> hi/lo bf16 Bt[N][K] (transpose). 32x32 tiles.
// ---------------------------------------------------------------------------
__global__ __launch_bounds__(256) void packBt_kernel(
    const float* __restrict__ W, __nv_bfloat16* __restrict__ H,
    __nv_bfloat16* __restrict__ L, int N, int K)
{
    __shared__ float tile[32][33];
    const int k0 = blockIdx.x * 32;
    const int n0 = blockIdx.y * 32;
    const int x = threadIdx.x, y = threadIdx.y;  // block (32, 8)

#pragma unroll
    for (int r = 0; r < 4; r++) {
        int row = y + r * 8;
        tile[row][x] = W[(size_t)(k0 + row) * N + n0 + x];
    }
    __syncthreads();
#pragma unroll
    for (int r = 0; r < 4; r++) {
        int n = y + r * 8;
        float f = tile[x][n];
        ushort h, l;
        split_bf16(f, h, l);
        size_t o = (size_t)(n0 + n) * K + k0 + x;
        H[o] = __ushort_as_bfloat16(h);
        L[o] = __ushort_as_bfloat16(l);
    }
}

// ---------------------------------------------------------------------------
// kv partial: kv[d][e] = sum_n k[n,d]*v[n,e] per (b,h,split)
// NSPLIT=32 (128 tokens/block), cp.async double-buffered.
// ---------------------------------------------------------------------------
#define KVCH 16

__global__ __launch_bounds__(256) void kv_partial_kernel(float* __restrict__ part)
{
    const int bh = blockIdx.x;
    const int split = blockIdx.y;
    const int b = bh / HEADS, h = bh % HEADS;
    const int n0 = split * (NTOK / NSPLIT);
    const int nstages = (NTOK / NSPLIT) / KVCH;

    __shared__ float ks[2][KVCH][DHEAD];
    __shared__ float vs[2][KVCH][DHEAD];

    const int tid = threadIdx.x;
    const int tx = tid % 16, ty = tid / 16;

    const float* base = g_qkv + (size_t)b * NTOK * QKVN;

    const int li = tid * 4;
    const int lr = li / DHEAD, lc = li % DHEAD;
    const uint32_t ks_a[2] = {smem_u32(&ks[0][lr][lc]), smem_u32(&ks[1][lr][lc])};
    const uint32_t vs_a[2] = {smem_u32(&vs[0][lr][lc]), smem_u32(&vs[1][lr][lc])};

    auto issue = [&](int s, int buf) {
        const float* p = base + (size_t)(n0 + s * KVCH + lr) * QKVN + h * DHEAD + lc;
        cp_async16(ks_a[buf], p + INNER);
        cp_async16(vs_a[buf], p + 2 * INNER);
        cp_commit();
    };

    float acc[4][4];
#pragma unroll
    for (int i = 0; i < 4; i++)
#pragma unroll
        for (int j = 0; j < 4; j++) acc[i][j] = 0.f;

    issue(0, 0);

    for (int s = 0; s < nstages; s++) {
        const int buf = s & 1;
        if (s + 1 < nstages) { issue(s + 1, buf ^ 1); cp_wait<1>(); }
        else                 { cp_wait<0>(); }
        __syncthreads();

#pragma unroll
        for (int nn = 0; nn < KVCH; nn++) {
            float rk[4], rv[4];
#pragma unroll
            for (int i = 0; i < 4; i++) rk[i] = ks[buf][nn][ty * 4 + i];
#pragma unroll
            for (int j = 0; j < 4; j++) rv[j] = vs[buf][nn][tx * 4 + j];
#pragma unroll
            for (int i = 0; i < 4; i++)
#pragma unroll
                for (int j = 0; j < 4; j++)
                    acc[i][j] += rk[i] * rv[j];
        }
        __syncthreads();
    }

    float* out = part + ((size_t)split * BATCH * HEADS + bh) * (DHEAD * DHEAD);
#pragma unroll
    for (int i = 0; i < 4; i++)
#pragma unroll
        for (int j = 0; j < 4; j++)
            out[(ty * 4 + i) * DHEAD + tx * 4 + j] = acc[i][j];
}

// ---------------------------------------------------------------------------
// kv finalize: C[d][e] = gamma_h^2 * kv[d][e] / ||kv[d,:]||
// ---------------------------------------------------------------------------
__global__ void kv_finalize_kernel(const float* __restrict__ gamma)
{
    const int bh = blockIdx.x;
    const int d = threadIdx.x;
    const int h = bh % HEADS;

    float row[DHEAD];
#pragma unroll
    for (int e = 0; e < DHEAD; e++) row[e] = 0.f;

    for (int s = 0; s < NSPLIT; s++) {
        const float* p = g_part + ((size_t)s * BATCH * HEADS + bh) * (DHEAD * DHEAD) + d * DHEAD;
#pragma unroll
        for (int e = 0; e < DHEAD; e++) row[e] += p[e];
    }
    float ss = 0.f;
#pragma unroll
    for (int e = 0; e < DHEAD; e++) ss += row[e] * row[e];

    const float g = gamma[h];
    const float scale = g * g / sqrtf(ss);

    float* out = g_C + (size_t)bh * DHEAD * DHEAD + d * DHEAD;
#pragma unroll
    for (int e = 0; e < DHEAD; e++) out[e] = row[e] * scale;
}

// ---------------------------------------------------------------------------
// apply: u = (q @ C) / ||q||, emits bf16 hi/lo streams for GEMM2 directly.
// ---------------------------------------------------------------------------
#define QPAD 68

__global__ __launch_bounds__(256) void apply_kernel(
    __nv_bfloat16* __restrict__ UH, __nv_bfloat16* __restrict__ UL)
{
    const int bh = blockIdx.x;
    const int chunk = blockIdx.y;
    const int b = bh / HEADS, h = bh % HEADS;

    __shared__ float Cs[DHEAD][DHEAD];
    __shared__ float qs[64][QPAD];
    __shared__ float inv[64];

    const int tid = threadIdx.x;
    const int n0 = chunk * 64;

#pragma unroll
    for (int i = tid * 4; i < DHEAD * DHEAD; i += 1024)
        *reinterpret_cast<float4*>(&Cs[0][0] + i) =
            *reinterpret_cast<const float4*>(g_C + (size_t)bh * DHEAD * DHEAD + i);

#pragma unroll
    for (int i = tid * 4; i < 64 * DHEAD; i += 1024) {
        int t = i / DHEAD, d = i % DHEAD;
        *reinterpret_cast<float4*>(&qs[t][d]) =
            *reinterpret_cast<const float4*>(g_qkv + (size_t)(b * NTOK + n0 + t) * QKVN + h * DHEAD + d);
    }
    __syncthreads();

    if (tid < 64) {
        float ss = 0.f;
#pragma unroll
        for (int d = 0; d < DHEAD; d++) { float x = qs[tid][d]; ss += x * x; }
        inv[tid] = 1.0f / sqrtf(ss);
    }
    __syncthreads();

    const int tx = tid % 16, ty = tid / 16;
    float acc[4][4];
#pragma unroll
    for (int i = 0; i < 4; i++)
#pragma unroll
        for (int j = 0; j < 4; j++) acc[i][j] = 0.f;

#pragma unroll
    for (int d = 0; d < DHEAD; d++) {
        float rq[4], rc[4];
#pragma unroll
        for (int i = 0; i < 4; i++) rq[i] = qs[ty * 4 + i][d];
#pragma unroll
        for (int j = 0; j < 4; j++) rc[j] = Cs[d][tx * 4 + j];
#pragma unroll
        for (int i = 0; i < 4; i++)
#pragma unroll
            for (int j = 0; j < 4; j++)
                acc[i][j] += rq[i] * rc[j];
    }

#pragma unroll
    for (int i = 0; i < 4; i++) {
        int t = ty * 4 + i;
        float s = inv[t];
        ushort hh[4], ll[4];
#pragma unroll
        for (int j = 0; j < 4; j++) split_bf16(acc[i][j] * s, hh[j], ll[j]);
        size_t o = (size_t)(b * NTOK + n0 + t) * INNER + h * DHEAD + tx * 4;
        *reinterpret_cast<uint2*>(UH + o) = *reinterpret_cast<uint2*>(hh);
        *reinterpret_cast<uint2*>(UL + o) = *reinterpret_cast<uint2*>(ll);
    }
}

// ---------------------------------------------------------------------------
extern "C" void kernel_launch(void* const* d_in, const int* in_sizes, int n_in,
                              void* d_out, int out_size)
{
    const float* x     = (const float*)d_in[0];
    const float* W_qkv = (const float*)d_in[1];
    const float* W_o   = (const float*)d_in[2];
    const float* b_o   = (const float*)d_in[3];
    const float* gamma = (const float*)d_in[4];
    float* out = (float*)d_out;

    static float* qkv_p = nullptr;
    static float* part_p = nullptr;
    static __nv_bfloat16 *xh, *xl, *uh, *ul, *wqh, *wql, *woh, *wol;
    if (!qkv_p) {
        cudaGetSymbolAddress((void**)&qkv_p, g_qkv);
        cudaGetSymbolAddress((void**)&part_p, g_part);
        cudaGetSymbolAddress((void**)&xh, g_xh);
        cudaGetSymbolAddress((void**)&xl, g_xl);
        cudaGetSymbolAddress((void**)&uh, g_uh);
        cudaGetSymbolAddress((void**)&ul, g_ul);
        cudaGetSymbolAddress((void**)&wqh, g_wqh);
        cudaGetSymbolAddress((void**)&wql, g_wql);
        cudaGetSymbolAddress((void**)&woh, g_woh);
        cudaGetSymbolAddress((void**)&wol, g_wol);
        cudaFuncSetAttribute(gemm_bf16x3_kernel,
                             cudaFuncAttributeMaxDynamicSharedMemorySize, GEMM_SMEM);
    }

    // 1) pack x and W_qkv
    packA_kernel<<<(size_t)MTOT * DIM / 2048, 256>>>(x, xh, xl);
    packBt_kernel<<<dim3(DIM / 32, QKVN / 32), dim3(32, 8)>>>(W_qkv, wqh, wql, QKVN, DIM);

    // 2) qkv = x @ W_qkv  (bf16x3 mma.sync)
    gemm_bf16x3_kernel<<<dim3(QKVN / 128, MTOT / 128), 256, GEMM_SMEM>>>(
        xh, xl, wqh, wql, qkv_p, nullptr, QKVN, DIM);

    // 3) kv partials, finalize, apply (apply emits packed u directly)
    kv_partial_kernel<<<dim3(BATCH * HEADS, NSPLIT), 256>>>(part_p);
    kv_finalize_kernel<<<BATCH * HEADS, DHEAD>>>(gamma);
    apply_kernel<<<dim3(BATCH * HEADS, NTOK / 64), 256>>>(uh, ul);

    // 4) pack W_o
    packBt_kernel<<<dim3(DIM / 32, INNER / 32), dim3(32, 8)>>>(W_o, woh, wol, INNER, DIM);

    // 5) out = u @ W_o + b_o  (bf16x3 mma.sync)
    gemm_bf16x3_kernel<<<dim3(INNER / 128, MTOT / 128), 256, GEMM_SMEM>>>(
        uh, ul, woh, wol, out, b_o, INNER, DIM);
}